// round 6
// baseline (speedup 1.0000x reference)
#include <cuda_runtime.h>
#include <math_constants.h>

// SoftMinLayer: W = 79998 windows (len 500, step 250); 5 segments of 100;
// banded DTW (|i-j|<=1) over squared-L2 costs; out = mean(exp(-0.01*sqrt(d))).
//
// FOUR windows per warp: 8-lane quarters, each quarter owns one window.
// 13 band-cell accumulators in packed f32x2; 6 unconditional slices + a
// 2-lane remainder. Width-8 fold tree (13 shfl) reduces all 13 cells for all
// 4 windows at once; 13 width-8 broadcasts feed a register DTW shared 4-way.

#define SEGC   5
#define TPB    256
#define NW     8          // warps per block
#define BLOCKS 444        // 3 * 148, persistent

typedef unsigned long long u64;

__device__ __forceinline__ u64 f2_fma(u64 a, u64 b, u64 c) {
    u64 d; asm("fma.rn.f32x2 %0, %1, %2, %3;" : "=l"(d) : "l"(a), "l"(b), "l"(c)); return d;
}
__device__ __forceinline__ u64 f2_add(u64 a, u64 b) {
    u64 d; asm("add.rn.f32x2 %0, %1, %2;" : "=l"(d) : "l"(a), "l"(b)); return d;
}
__device__ __forceinline__ float f2_hadd(u64 v) {
    float lo, hi; asm("mov.b64 {%0, %1}, %2;" : "=f"(lo), "=f"(hi) : "l"(v));
    return lo + hi;
}

__device__ __forceinline__ float foldstep(float A, float B, bool p, int o) {
    float v = p ? B : A;
    float u = p ? A : B;
    return v + __shfl_xor_sync(0xffffffffu, u, o);
}
// After the 3-level width-8 fold, stream n sits at lane bitrev3(n) in each
// quarter (n taken mod 8; streams 8..12 live in the second fold output).
#define SRCLANE8(n) ((((n) >> 2) & 1) | ((((n) >> 1) & 1) << 1) | (((n) & 1) << 2))

__global__ void zero_kernel(float* out) { out[0] = 0.0f; }

__global__ __launch_bounds__(TPB, 3)
void softmin_kernel(const float* __restrict__ x, const float* __restrict__ S,
                    float* __restrict__ out, int W, float invW)
{
    __shared__ float ssf[SEGC * 100];   // -S
    __shared__ float sred[NW];

    const int t = threadIdx.x;
    for (int i = t; i < SEGC * 100; i += TPB) ssf[i] = -S[i];
    __syncthreads();
    const u64* ss2 = reinterpret_cast<const u64*>(ssf);   // [m*50 + idx]

    const int lane = t & 31, warp = t >> 5;
    const int h    = lane >> 3;        // quarter id: which window of the 4
    const int sub  = lane & 7;         // lane within quarter
    const int gw   = blockIdx.x * NW + warp;
    const int TW   = gridDim.x * NW;
    const int NP   = (W + 3) >> 2;

    const bool p4 = (lane & 4) != 0;
    const bool p2 = (lane & 2) != 0;
    const bool p1 = (lane & 1) != 0;

    float xsum = 0.0f;

    for (int p = gw; p < NP; p += TW) {
        const int w  = 4 * p + h;
        const int wc = (w < W) ? w : (W - 1);
        const u64* xw = reinterpret_cast<const u64*>(x) + (size_t)wc * 125u;

        u64 acc[13];
#pragma unroll
        for (int c = 0; c < 13; ++c) acc[c] = 0ull;

        // cell ids: (m,m)=3m ; (m,m-1)=3m-1 ; (m-1,m)=3m-2
#pragma unroll
        for (int k = 0; k < 6; ++k) {
            const int idx = sub + 8 * k;          // <= 47 < 50: unconditional
            u64 xv[SEGC], sv[SEGC];
#pragma unroll
            for (int m = 0; m < SEGC; ++m) xv[m] = xw[m * 50 + idx];
#pragma unroll
            for (int m = 0; m < SEGC; ++m) sv[m] = ss2[m * 50 + idx];
#pragma unroll
            for (int m = 0; m < SEGC; ++m) {
                { u64 d = f2_add(xv[m], sv[m]); acc[3 * m] = f2_fma(d, d, acc[3 * m]); }
                if (m > 0) {
                    { u64 d = f2_add(xv[m], sv[m - 1]); acc[3 * m - 1] = f2_fma(d, d, acc[3 * m - 1]); }
                    { u64 d = f2_add(xv[m - 1], sv[m]); acc[3 * m - 2] = f2_fma(d, d, acc[3 * m - 2]); }
                }
            }
        }
        // remainder: idx 48, 49 handled by sub = 0, 1 of each quarter
        if (sub < 2) {
            const int idx = 48 + sub;
            u64 xv[SEGC], sv[SEGC];
#pragma unroll
            for (int m = 0; m < SEGC; ++m) xv[m] = xw[m * 50 + idx];
#pragma unroll
            for (int m = 0; m < SEGC; ++m) sv[m] = ss2[m * 50 + idx];
#pragma unroll
            for (int m = 0; m < SEGC; ++m) {
                { u64 d = f2_add(xv[m], sv[m]); acc[3 * m] = f2_fma(d, d, acc[3 * m]); }
                if (m > 0) {
                    { u64 d = f2_add(xv[m], sv[m - 1]); acc[3 * m - 1] = f2_fma(d, d, acc[3 * m - 1]); }
                    { u64 d = f2_add(xv[m - 1], sv[m]); acc[3 * m - 2] = f2_fma(d, d, acc[3 * m - 2]); }
                }
            }
        }

        // horizontal f32x2 add -> 13 per-lane partials
        float a0  = f2_hadd(acc[0]),  a1  = f2_hadd(acc[1]),  a2  = f2_hadd(acc[2]);
        float a3  = f2_hadd(acc[3]),  a4  = f2_hadd(acc[4]),  a5  = f2_hadd(acc[5]);
        float a6  = f2_hadd(acc[6]),  a7  = f2_hadd(acc[7]),  a8  = f2_hadd(acc[8]);
        float a9  = f2_hadd(acc[9]),  a10 = f2_hadd(acc[10]), a11 = f2_hadd(acc[11]);
        float a12 = f2_hadd(acc[12]);

        // width-8 fold tree: 13 shfl reduce all 13 streams per quarter
        float q0 = foldstep(a0,  a1,  p4, 4);
        float q1 = foldstep(a2,  a3,  p4, 4);
        float q2 = foldstep(a4,  a5,  p4, 4);
        float q3 = foldstep(a6,  a7,  p4, 4);
        float q4 = foldstep(a8,  a9,  p4, 4);
        float q5 = foldstep(a10, a11, p4, 4);
        float q6 = foldstep(a12, 0.0f, p4, 4);

        float r0 = foldstep(q0, q1, p2, 2);
        float r1 = foldstep(q2, q3, p2, 2);
        float r2 = foldstep(q4, q5, p2, 2);
        float r3 = foldstep(q6, 0.0f, p2, 2);

        float t0 = foldstep(r0, r1, p1, 1);   // streams 0..7  at lane bitrev3(n)
        float t1 = foldstep(r2, r3, p1, 1);   // streams 8..12 at lane bitrev3(n-8)

        // width-8 broadcasts
        float C13[13];
#pragma unroll
        for (int n = 0; n < 8; ++n)
            C13[n] = __shfl_sync(0xffffffffu, t0, SRCLANE8(n), 8);
#pragma unroll
        for (int n = 8; n < 13; ++n)
            C13[n] = __shfl_sync(0xffffffffu, t1, SRCLANE8(n - 8), 8);

        float C[SEGC][3];
#pragma unroll
        for (int i = 0; i < SEGC; ++i) {
#pragma unroll
            for (int jo = 0; jo < 3; ++jo) {
                const int j = i + jo - 1;
                if (j >= 0 && j < SEGC) {
                    const int c = (j == i) ? 3 * i : ((j < i) ? 3 * i - 1 : 3 * i + 1);
                    C[i][jo] = C13[c];
                } else {
                    C[i][jo] = 0.0f;
                }
            }
        }

        // banded DTW, fully unrolled in registers
        const float INF = CUDART_INF_F;
        float row[SEGC + 1];
        row[0] = 0.0f;
#pragma unroll
        for (int r = 1; r <= SEGC; ++r) row[r] = INF;
#pragma unroll
        for (int i = 0; i < SEGC; ++i) {
            float nrow[SEGC + 1];
#pragma unroll
            for (int r = 0; r <= SEGC; ++r) nrow[r] = INF;
            const int lo = (i > 0) ? (i - 1) : 0;
            const int hi = (i + 1 < SEGC) ? (i + 1) : (SEGC - 1);
#pragma unroll
            for (int j = 0; j < SEGC; ++j) {
                if (j >= lo && j <= hi) {
                    float prev = fminf(fminf(row[j + 1], nrow[j]), row[j]);
                    nrow[j + 1] = C[i][j - i + 1] + prev;
                }
            }
#pragma unroll
            for (int r = 0; r <= SEGC; ++r) row[r] = nrow[r];
        }

        float xi = __expf(-0.01f * sqrtf(row[SEGC]));
        if (w < W) xsum += xi;        // uniform within each quarter
    }

    // epilogue: lane 0 of each quarter carries its quarter's sum
    float v = (sub == 0) ? xsum : 0.0f;
    v += __shfl_xor_sync(0xffffffffu, v, 16);
    v += __shfl_xor_sync(0xffffffffu, v, 8);
    v += __shfl_xor_sync(0xffffffffu, v, 4);
    v += __shfl_xor_sync(0xffffffffu, v, 2);
    v += __shfl_xor_sync(0xffffffffu, v, 1);
    if ((t & 31) == 0) sred[warp] = v;
    __syncthreads();
    if (t == 0) {
        float s = 0.0f;
#pragma unroll
        for (int i = 0; i < NW; ++i) s += sred[i];
        atomicAdd(out, s * invW);
    }
}

extern "C" void kernel_launch(void* const* d_in, const int* in_sizes, int n_in,
                              void* d_out, int out_size)
{
    const float* x = (const float*)d_in[0];
    const float* S = (const float*)d_in[1];
    float* out = (float*)d_out;

    const int Q    = in_sizes[0];
    const int L    = in_sizes[1];       // 500
    const int step = L / 2;             // 250
    const int W    = (Q - L + step - 1) / step;   // 79998
    const float invW = 1.0f / (float)W;

    zero_kernel<<<1, 1>>>(out);
    softmin_kernel<<<BLOCKS, TPB>>>(x, S, out, W, invW);
}

// round 7
// speedup vs baseline: 1.1604x; 1.1604x over previous
#include <cuda_runtime.h>
#include <math_constants.h>

// SoftMinLayer: W = 79998 windows (len 500, step 250); 5 segments of 100;
// banded DTW (|i-j|<=1) over squared-L2 costs; out = mean(exp(-0.01*sqrt(d))).
//
// TWO windows per warp (16-lane halves), persistent. Row-major band order:
// for x-segment m, cells (m,m-1),(m,m),(m,m+1) all reuse the same xv regs;
// S slices re-read from smem per cell (broadcast LDS) -> no carry registers,
// fits 64 regs -> 4 CTAs/SM. Width-16 fold tree reduces all 13 cells at once.

#define SEGC   5
#define TPB    256
#define NW     8          // warps per block
#define BLOCKS 592        // 4 * 148, persistent

typedef unsigned long long u64;

__device__ __forceinline__ u64 f2_fma(u64 a, u64 b, u64 c) {
    u64 d; asm("fma.rn.f32x2 %0, %1, %2, %3;" : "=l"(d) : "l"(a), "l"(b), "l"(c)); return d;
}
__device__ __forceinline__ u64 f2_add(u64 a, u64 b) {
    u64 d; asm("add.rn.f32x2 %0, %1, %2;" : "=l"(d) : "l"(a), "l"(b)); return d;
}
__device__ __forceinline__ float f2_hadd(u64 v) {
    float lo, hi; asm("mov.b64 {%0, %1}, %2;" : "=f"(lo), "=f"(hi) : "l"(v));
    return lo + hi;
}

__device__ __forceinline__ float foldstep(float A, float B, bool p, int o) {
    float v = p ? B : A;
    float u = p ? A : B;
    return v + __shfl_xor_sync(0xffffffffu, u, o);
}
// After the 4-level width-16 fold, cell n sits at lane (within each half):
#define SRCLANE16(n) ((((n) & 1) << 3) | ((((n) >> 1) & 1) << 2) | \
                      ((((n) >> 2) & 1) << 1) | (((n) >> 3) & 1))

__global__ void zero_kernel(float* out) { out[0] = 0.0f; }

__global__ __launch_bounds__(TPB, 4)
void softmin_kernel(const float* __restrict__ x, const float* __restrict__ S,
                    float* __restrict__ out, int W, float invW)
{
    __shared__ float ssf[SEGC * 128];   // -S, segments padded 100 -> 128 (zeros)
    __shared__ float sred[NW];

    const int t = threadIdx.x;
    for (int i = t; i < SEGC * 128; i += TPB) {
        int seg = i >> 7, off = i & 127;
        ssf[i] = (off < 100) ? -S[seg * 100 + off] : 0.0f;
    }
    __syncthreads();
    const u64* ss2 = reinterpret_cast<const u64*>(ssf);   // [seg*64 + idx]

    const int lane = t & 31, warp = t >> 5;
    const int h    = lane >> 4;        // which window of the pair
    const int sub  = lane & 15;        // lane within half
    const int gw   = blockIdx.x * NW + warp;
    const int TW   = gridDim.x * NW;
    const int NP   = (W + 1) >> 1;

    const bool p8 = (lane & 8) != 0;
    const bool p4 = (lane & 4) != 0;
    const bool p2 = (lane & 2) != 0;
    const bool p1 = (lane & 1) != 0;

    float xsum = 0.0f;

    for (int p = gw; p < NP; p += TW) {
        const int w  = 2 * p + h;
        const int wc = (w < W) ? w : (W - 1);
        const u64* xw = reinterpret_cast<const u64*>(x) + (size_t)wc * 125u;

        u64 acc[13];
#pragma unroll
        for (int c = 0; c < 13; ++c) acc[c] = 0ull;

        // Row m cells: (m,m-1)=3m-1, (m,m)=3m, (m,m+1)=3m+1. Same xv for all.
#pragma unroll
        for (int m = 0; m < SEGC; ++m) {
            u64 xv[4];
#pragma unroll
            for (int k = 0; k < 4; ++k) {
                const int idx = sub + 16 * k;
                xv[k] = (idx < 50) ? xw[m * 50 + idx] : 0ull;   // 50 f2/segment
            }
            if (m > 0) {
#pragma unroll
                for (int k = 0; k < 4; ++k) {
                    const int idx = sub + 16 * k;
                    u64 sv = ss2[(m - 1) * 64 + idx];           // zero-padded
                    u64 d = f2_add(xv[k], sv);
                    acc[3 * m - 1] = f2_fma(d, d, acc[3 * m - 1]);
                }
            }
#pragma unroll
            for (int k = 0; k < 4; ++k) {
                const int idx = sub + 16 * k;
                u64 sv = ss2[m * 64 + idx];
                u64 d = f2_add(xv[k], sv);
                acc[3 * m] = f2_fma(d, d, acc[3 * m]);
            }
            if (m < SEGC - 1) {
#pragma unroll
                for (int k = 0; k < 4; ++k) {
                    const int idx = sub + 16 * k;
                    u64 sv = ss2[(m + 1) * 64 + idx];
                    u64 d = f2_add(xv[k], sv);
                    acc[3 * m + 1] = f2_fma(d, d, acc[3 * m + 1]);
                }
            }
        }

        // horizontal f32x2 add -> 13 per-lane partials
        float a0  = f2_hadd(acc[0]),  a1  = f2_hadd(acc[1]),  a2  = f2_hadd(acc[2]);
        float a3  = f2_hadd(acc[3]),  a4  = f2_hadd(acc[4]),  a5  = f2_hadd(acc[5]);
        float a6  = f2_hadd(acc[6]),  a7  = f2_hadd(acc[7]),  a8  = f2_hadd(acc[8]);
        float a9  = f2_hadd(acc[9]),  a10 = f2_hadd(acc[10]), a11 = f2_hadd(acc[11]);
        float a12 = f2_hadd(acc[12]);

        // width-16 fold tree: 14 shfl reduce all 13 cells (per half)
        float q0 = foldstep(a0,  a1,  p8, 8);
        float q1 = foldstep(a2,  a3,  p8, 8);
        float q2 = foldstep(a4,  a5,  p8, 8);
        float q3 = foldstep(a6,  a7,  p8, 8);
        float q4 = foldstep(a8,  a9,  p8, 8);
        float q5 = foldstep(a10, a11, p8, 8);
        float q6 = foldstep(a12, 0.0f, p8, 8);

        float r0 = foldstep(q0, q1, p4, 4);
        float r1 = foldstep(q2, q3, p4, 4);
        float r2 = foldstep(q4, q5, p4, 4);
        float r3 = foldstep(q6, 0.0f, p4, 4);

        float t0 = foldstep(r0, r1, p2, 2);
        float t1 = foldstep(r2, r3, p2, 2);

        float fin = foldstep(t0, t1, p1, 1);

        // broadcast within each 16-lane half
        float C13[13];
#pragma unroll
        for (int n = 0; n < 13; ++n)
            C13[n] = __shfl_sync(0xffffffffu, fin, SRCLANE16(n), 16);

        float C[SEGC][3];
#pragma unroll
        for (int i = 0; i < SEGC; ++i) {
#pragma unroll
            for (int jo = 0; jo < 3; ++jo) {
                const int j = i + jo - 1;
                if (j >= 0 && j < SEGC) {
                    const int c = (j == i) ? 3 * i : ((j < i) ? 3 * i - 1 : 3 * i + 1);
                    C[i][jo] = C13[c];
                } else {
                    C[i][jo] = 0.0f;
                }
            }
        }

        // banded DTW, fully unrolled in registers
        const float INF = CUDART_INF_F;
        float row[SEGC + 1];
        row[0] = 0.0f;
#pragma unroll
        for (int r = 1; r <= SEGC; ++r) row[r] = INF;
#pragma unroll
        for (int i = 0; i < SEGC; ++i) {
            float nrow[SEGC + 1];
#pragma unroll
            for (int r = 0; r <= SEGC; ++r) nrow[r] = INF;
            const int lo = (i > 0) ? (i - 1) : 0;
            const int hi = (i + 1 < SEGC) ? (i + 1) : (SEGC - 1);
#pragma unroll
            for (int j = 0; j < SEGC; ++j) {
                if (j >= lo && j <= hi) {
                    float prev = fminf(fminf(row[j + 1], nrow[j]), row[j]);
                    nrow[j + 1] = C[i][j - i + 1] + prev;
                }
            }
#pragma unroll
            for (int r = 0; r <= SEGC; ++r) row[r] = nrow[r];
        }

        float xi = __expf(-0.01f * sqrtf(row[SEGC]));
        if (w < W) xsum += xi;        // uniform within each half
    }

    // epilogue: lane 0 of each half carries its half's sum
    float v = (sub == 0) ? xsum : 0.0f;
    v += __shfl_xor_sync(0xffffffffu, v, 16);
    v += __shfl_xor_sync(0xffffffffu, v, 8);
    v += __shfl_xor_sync(0xffffffffu, v, 4);
    v += __shfl_xor_sync(0xffffffffu, v, 2);
    v += __shfl_xor_sync(0xffffffffu, v, 1);
    if ((t & 31) == 0) sred[warp] = v;
    __syncthreads();
    if (t == 0) {
        float s = 0.0f;
#pragma unroll
        for (int i = 0; i < NW; ++i) s += sred[i];
        atomicAdd(out, s * invW);
    }
}

extern "C" void kernel_launch(void* const* d_in, const int* in_sizes, int n_in,
                              void* d_out, int out_size)
{
    const float* x = (const float*)d_in[0];
    const float* S = (const float*)d_in[1];
    float* out = (float*)d_out;

    const int Q    = in_sizes[0];
    const int L    = in_sizes[1];       // 500
    const int step = L / 2;             // 250
    const int W    = (Q - L + step - 1) / step;   // 79998
    const float invW = 1.0f / (float)W;

    zero_kernel<<<1, 1>>>(out);
    softmin_kernel<<<BLOCKS, TPB>>>(x, S, out, W, invW);
}